// round 11
// baseline (speedup 1.0000x reference)
#include <cuda_runtime.h>
#include <cuda_fp16.h>

// Problem constants (fixed shapes from reference)
#define VV 100000
#define DD 64
#define BB 4096
#define LL 50
#define KK 3
#define NBAGS (BB * (2 + KK))   // 20480
#define MAX_NORM 20.0f

// Renormed embedding table in fp16 (12.8 MB).
__device__ __half d_table[VV * DD];

// Kernel 1: renorm rows. 8 lanes per row; each lane reads 8 floats (2x float4),
// reduces norm across 8 lanes, writes 8 halves (uint4, 16 B).
__global__ __launch_bounds__(256) void renorm_kernel(const float* __restrict__ emb) {
    int idx  = blockIdx.x * blockDim.x + threadIdx.x;
    int row  = idx >> 3;
    int lane = threadIdx.x & 7;
    if (row >= VV) return;

    const float4* e4 = (const float4*)emb;
    float4 v0 = e4[row * 16 + lane * 2 + 0];
    float4 v1 = e4[row * 16 + lane * 2 + 1];

    float ss = v0.x*v0.x + v0.y*v0.y + v0.z*v0.z + v0.w*v0.w
             + v1.x*v1.x + v1.y*v1.y + v1.z*v1.z + v1.w*v1.w;
    ss += __shfl_xor_sync(0xffffffffu, ss, 1);
    ss += __shfl_xor_sync(0xffffffffu, ss, 2);
    ss += __shfl_xor_sync(0xffffffffu, ss, 4);

    float norm = sqrtf(ss);
    float s = (norm > MAX_NORM) ? (MAX_NORM / norm) : 1.0f;

    __half2 h0 = __floats2half2_rn(v0.x * s, v0.y * s);
    __half2 h1 = __floats2half2_rn(v0.z * s, v0.w * s);
    __half2 h2 = __floats2half2_rn(v1.x * s, v1.y * s);
    __half2 h3 = __floats2half2_rn(v1.z * s, v1.w * s);
    uint4 packed;
    packed.x = *reinterpret_cast<unsigned*>(&h0);
    packed.y = *reinterpret_cast<unsigned*>(&h1);
    packed.z = *reinterpret_cast<unsigned*>(&h2);
    packed.w = *reinterpret_cast<unsigned*>(&h3);
    ((uint4*)d_table)[row * 8 + lane] = packed;
}

// Kernel 2: embedding-bag sum. ONE WARP PER BAG (R7 configuration) with int2
// token loads: rounds of 8 tokens, sub s loads tokens {t+2s, t+2s+1} with one
// LDG.64 (p is 8 B-aligned: bag*200 B offset), then issues two uint4 gathers
// (4 x 128 B lines per warp-gather-LDG). Token LDGs per thread: 13 -> 7.
// 13 gather-LDGs per bag (structural minimum), 2-round shfl-xor reduction.
// Bag order matches output tuple flatten: [l (B) | r (B) | neg (B*K)].
__global__ __launch_bounds__(256) void bag_kernel(
    const int* __restrict__ tl,
    const int* __restrict__ tr,
    const int* __restrict__ tn,
    float* __restrict__ out)
{
    int warp  = threadIdx.x >> 5;
    int lane  = threadIdx.x & 31;
    int sub   = lane >> 3;     // token-pair slot 0..3 within a round
    int dlane = lane & 7;      // which 16 B of the 128 B row
    int bag   = blockIdx.x * 8 + warp;
    if (bag >= NBAGS) return;

    const int* p;
    if (bag < BB)          p = tl + bag * LL;
    else if (bag < 2 * BB) p = tr + (bag - BB) * LL;
    else                   p = tn + (bag - 2 * BB) * LL;

    const uint4* t4 = (const uint4*)d_table;   // 8 uint4 per row
    float acc[8] = {0.f, 0.f, 0.f, 0.f, 0.f, 0.f, 0.f, 0.f};

    // 6 rounds of 8 tokens (48 tokens)
    #pragma unroll
    for (int t = 0; t < 48; t += 8) {
        int2 tk = __ldg((const int2*)(p + t + 2 * sub));   // 8 B-aligned

        uint4 va = __ldg(&t4[tk.x * 8 + dlane]);
        uint4 vb = __ldg(&t4[tk.y * 8 + dlane]);

        float2 a0 = __half22float2(*reinterpret_cast<__half2*>(&va.x));
        float2 a1 = __half22float2(*reinterpret_cast<__half2*>(&va.y));
        float2 a2 = __half22float2(*reinterpret_cast<__half2*>(&va.z));
        float2 a3 = __half22float2(*reinterpret_cast<__half2*>(&va.w));
        acc[0] += a0.x; acc[1] += a0.y; acc[2] += a1.x; acc[3] += a1.y;
        acc[4] += a2.x; acc[5] += a2.y; acc[6] += a3.x; acc[7] += a3.y;

        float2 b0 = __half22float2(*reinterpret_cast<__half2*>(&vb.x));
        float2 b1 = __half22float2(*reinterpret_cast<__half2*>(&vb.y));
        float2 b2 = __half22float2(*reinterpret_cast<__half2*>(&vb.z));
        float2 b3 = __half22float2(*reinterpret_cast<__half2*>(&vb.w));
        acc[0] += b0.x; acc[1] += b0.y; acc[2] += b1.x; acc[3] += b1.y;
        acc[4] += b2.x; acc[5] += b2.y; acc[6] += b3.x; acc[7] += b3.y;
    }
    // tail: tokens 48,49 handled by subs 0,1 (scalar token load, one gather)
    if (sub < 2) {
        int tok = __ldg(p + 48 + sub);
        uint4 v = __ldg(&t4[tok * 8 + dlane]);
        float2 f0 = __half22float2(*reinterpret_cast<__half2*>(&v.x));
        float2 f1 = __half22float2(*reinterpret_cast<__half2*>(&v.y));
        float2 f2 = __half22float2(*reinterpret_cast<__half2*>(&v.z));
        float2 f3 = __half22float2(*reinterpret_cast<__half2*>(&v.w));
        acc[0] += f0.x; acc[1] += f0.y; acc[2] += f1.x; acc[3] += f1.y;
        acc[4] += f2.x; acc[5] += f2.y; acc[6] += f3.x; acc[7] += f3.y;
    }

    // Combine the 4 sub-group partials (lane bits 3,4 index sub).
    #pragma unroll
    for (int i = 0; i < 8; ++i) {
        acc[i] += __shfl_xor_sync(0xffffffffu, acc[i], 8);
        acc[i] += __shfl_xor_sync(0xffffffffu, acc[i], 16);
    }

    // acc[i] on this lane = dim dlane*8 + i (replicated across sub).
    // Each lane writes 2 dims: dims dlane*8 + sub*2 + {0,1} -> 256 B/warp contiguous.
    float2 w = make_float2(acc[sub * 2], acc[sub * 2 + 1]);
    ((float2*)out)[bag * 32 + dlane * 4 + sub] = w;
}

extern "C" void kernel_launch(void* const* d_in, const int* in_sizes, int n_in,
                              void* d_out, int out_size) {
    const float* emb = (const float*)d_in[0];
    const int*   tl  = (const int*)d_in[1];
    const int*   tr  = (const int*)d_in[2];
    const int*   tn  = (const int*)d_in[3];
    float*       out = (float*)d_out;

    int renorm_blocks = (VV * 8 + 255) / 256;    // 3125 (32 rows per block)
    renorm_kernel<<<renorm_blocks, 256>>>(emb);

    int bag_blocks = NBAGS / 8;                  // 2560 (8 warps = 8 bags per block)
    bag_kernel<<<bag_blocks, 256>>>(tl, tr, tn, out);
}

// round 12
// speedup vs baseline: 1.0169x; 1.0169x over previous
#include <cuda_runtime.h>
#include <cuda_fp16.h>

// Problem constants (fixed shapes from reference)
#define VV 100000
#define DD 64
#define BB 4096
#define LL 50
#define KK 3
#define NBAGS (BB * (2 + KK))   // 20480
#define MAX_NORM 20.0f

#define BAG_CTAS 1184            // 148 SMs * 8 resident CTAs -> exactly one wave

// Renormed embedding table in fp16 (12.8 MB).
__device__ __half d_table[VV * DD];

// Kernel 1: renorm rows. 8 lanes per row; each lane reads 8 floats (2x float4),
// reduces norm across 8 lanes, writes 8 halves (uint4, 16 B).
__global__ __launch_bounds__(256) void renorm_kernel(const float* __restrict__ emb) {
    int idx  = blockIdx.x * blockDim.x + threadIdx.x;
    int row  = idx >> 3;
    int lane = threadIdx.x & 7;
    if (row >= VV) return;

    const float4* e4 = (const float4*)emb;
    float4 v0 = e4[row * 16 + lane * 2 + 0];
    float4 v1 = e4[row * 16 + lane * 2 + 1];

    float ss = v0.x*v0.x + v0.y*v0.y + v0.z*v0.z + v0.w*v0.w
             + v1.x*v1.x + v1.y*v1.y + v1.z*v1.z + v1.w*v1.w;
    ss += __shfl_xor_sync(0xffffffffu, ss, 1);
    ss += __shfl_xor_sync(0xffffffffu, ss, 2);
    ss += __shfl_xor_sync(0xffffffffu, ss, 4);

    float norm = sqrtf(ss);
    float s = (norm > MAX_NORM) ? (MAX_NORM / norm) : 1.0f;

    __half2 h0 = __floats2half2_rn(v0.x * s, v0.y * s);
    __half2 h1 = __floats2half2_rn(v0.z * s, v0.w * s);
    __half2 h2 = __floats2half2_rn(v1.x * s, v1.y * s);
    __half2 h3 = __floats2half2_rn(v1.z * s, v1.w * s);
    uint4 packed;
    packed.x = *reinterpret_cast<unsigned*>(&h0);
    packed.y = *reinterpret_cast<unsigned*>(&h1);
    packed.z = *reinterpret_cast<unsigned*>(&h2);
    packed.w = *reinterpret_cast<unsigned*>(&h3);
    ((uint4*)d_table)[row * 8 + lane] = packed;
}

// Kernel 2: embedding-bag sum. PERSISTENT grid (one wave, 1184 CTAs) with a
// grid-stride loop over bags; each warp processes 2-3 bags sequentially.
// Inner body is the verified-optimal R7 shape: the warp's four 8-lane groups
// each gather a DIFFERENT token per iteration (uint4 = 16 B/lane -> 4 x 128 B
// lines per warp-LDG), 13 gather-LDGs/bag, 2-round shfl-xor reduction.
// Bag order matches output tuple flatten: [l (B) | r (B) | neg (B*K)].
__global__ __launch_bounds__(256) void bag_kernel(
    const int* __restrict__ tl,
    const int* __restrict__ tr,
    const int* __restrict__ tn,
    float* __restrict__ out)
{
    int warp  = threadIdx.x >> 5;
    int lane  = threadIdx.x & 31;
    int sub   = lane >> 3;     // token slot 0..3 within an iteration
    int dlane = lane & 7;      // which 16 B of the 128 B row

    const uint4* t4 = (const uint4*)d_table;   // 8 uint4 per row
    const int nwarps = BAG_CTAS * 8;

    for (int bag = blockIdx.x * 8 + warp; bag < NBAGS; bag += nwarps) {
        const int* p;
        if (bag < BB)          p = tl + bag * LL;
        else if (bag < 2 * BB) p = tr + (bag - BB) * LL;
        else                   p = tn + (bag - 2 * BB) * LL;

        float acc[8] = {0.f, 0.f, 0.f, 0.f, 0.f, 0.f, 0.f, 0.f};

        // 12 full iterations of 4 tokens
        #pragma unroll
        for (int t = 0; t < 48; t += 4) {
            int tok = p[t + sub];                  // uniform across 8-lane group
            uint4 v = __ldg(&t4[tok * 8 + dlane]);
            __half2 a = *reinterpret_cast<__half2*>(&v.x);
            __half2 b = *reinterpret_cast<__half2*>(&v.y);
            __half2 c = *reinterpret_cast<__half2*>(&v.z);
            __half2 d = *reinterpret_cast<__half2*>(&v.w);
            float2 fa = __half22float2(a);
            float2 fb = __half22float2(b);
            float2 fc = __half22float2(c);
            float2 fd = __half22float2(d);
            acc[0] += fa.x; acc[1] += fa.y;
            acc[2] += fb.x; acc[3] += fb.y;
            acc[4] += fc.x; acc[5] += fc.y;
            acc[6] += fd.x; acc[7] += fd.y;
        }
        // tail: tokens 48,49 handled by sub 0,1 only
        if (sub < 2) {
            int tok = p[48 + sub];
            uint4 v = __ldg(&t4[tok * 8 + dlane]);
            __half2 a = *reinterpret_cast<__half2*>(&v.x);
            __half2 b = *reinterpret_cast<__half2*>(&v.y);
            __half2 c = *reinterpret_cast<__half2*>(&v.z);
            __half2 d = *reinterpret_cast<__half2*>(&v.w);
            float2 fa = __half22float2(a);
            float2 fb = __half22float2(b);
            float2 fc = __half22float2(c);
            float2 fd = __half22float2(d);
            acc[0] += fa.x; acc[1] += fa.y;
            acc[2] += fb.x; acc[3] += fb.y;
            acc[4] += fc.x; acc[5] += fc.y;
            acc[6] += fd.x; acc[7] += fd.y;
        }

        // Combine the 4 sub-group partials (lane bits 3,4 index sub).
        #pragma unroll
        for (int i = 0; i < 8; ++i) {
            acc[i] += __shfl_xor_sync(0xffffffffu, acc[i], 8);
            acc[i] += __shfl_xor_sync(0xffffffffu, acc[i], 16);
        }

        // acc[i] on this lane = dim dlane*8 + i (replicated across sub).
        // Each lane writes 2 dims -> 256 B/warp contiguous.
        float2 w = make_float2(acc[sub * 2], acc[sub * 2 + 1]);
        ((float2*)out)[bag * 32 + dlane * 4 + sub] = w;
    }
}

extern "C" void kernel_launch(void* const* d_in, const int* in_sizes, int n_in,
                              void* d_out, int out_size) {
    const float* emb = (const float*)d_in[0];
    const int*   tl  = (const int*)d_in[1];
    const int*   tr  = (const int*)d_in[2];
    const int*   tn  = (const int*)d_in[3];
    float*       out = (float*)d_out;

    int renorm_blocks = (VV * 8 + 255) / 256;    // 3125 (32 rows per block)
    renorm_kernel<<<renorm_blocks, 256>>>(emb);

    bag_kernel<<<BAG_CTAS, 256>>>(tl, tr, tn, out);
}